// round 2
// baseline (speedup 1.0000x reference)
#include <cuda_runtime.h>
#include <math.h>

#define Bn   8
#define Nn   16384
#define Cn   128
#define OUTn 256
#define En   262144

// ---- scratch (static device globals; no allocation allowed) ----
__device__ int   g_deg[Nn];
__device__ int   g_off[Nn + 1];
__device__ int   g_cur[Nn];
__device__ int   g_csr[En];
__device__ int   g_is64;
__device__ float g_aggr[(size_t)Bn * Nn * Cn];   // 64 MB

// ============================================================
// Dtype detection: int64 vs int32 edge_index.
// If buffer is true int64 (little-endian), high words are 0 (indices < 16384).
// If it's int32 data, "high words" are random indices, ~never all zero.
// ============================================================
__global__ void detect_kernel(const unsigned int* __restrict__ ei_raw) {
    int hi_zero = 0;
    for (int i = 0; i < 256; i++)
        if (ei_raw[2 * i + 1] == 0) hi_zero++;
    g_is64 = (hi_zero >= 250) ? 1 : 0;
}

__device__ __forceinline__ int load_idx(const void* ei, int pos, int is64) {
    if (is64) return (int)((const long long*)ei)[pos];
    return ((const int*)ei)[pos];
}

// ============================================================
// CSR build: histogram -> scan -> scatter
// ============================================================
__global__ void init_kernel() {
    int i = blockIdx.x * blockDim.x + threadIdx.x;
    if (i < Nn) { g_deg[i] = 0; g_cur[i] = 0; }
}

__global__ void count_kernel(const void* __restrict__ ei) {
    int e = blockIdx.x * blockDim.x + threadIdx.x;
    int is64 = g_is64;
    if (e < En) {
        int r = load_idx(ei, e, is64);
        if ((unsigned)r < Nn) atomicAdd(&g_deg[r], 1);
    }
}

// exclusive prefix sum over N=16384 = 1024 threads x 16 each
__global__ void scan_kernel() {
    __shared__ int s[1024];
    int t = threadIdx.x;
    int base = t * 16;
    int local[16];
    int sum = 0;
#pragma unroll
    for (int i = 0; i < 16; i++) { local[i] = sum; sum += g_deg[base + i]; }
    s[t] = sum;
    __syncthreads();
    for (int off = 1; off < 1024; off <<= 1) {
        int v = (t >= off) ? s[t - off] : 0;
        __syncthreads();
        s[t] += v;
        __syncthreads();
    }
    int pre = (t > 0) ? s[t - 1] : 0;
#pragma unroll
    for (int i = 0; i < 16; i++) g_off[base + i] = pre + local[i];
    if (t == 1023) g_off[Nn] = s[1023];
}

__global__ void scatter_kernel(const void* __restrict__ ei) {
    int e = blockIdx.x * blockDim.x + threadIdx.x;
    int is64 = g_is64;
    if (e < En) {
        int r = load_idx(ei, e, is64);
        int c = load_idx(ei, En + e, is64);
        if ((unsigned)r < Nn && (unsigned)c < Nn) {
            int p = atomicAdd(&g_cur[r], 1);
            g_csr[g_off[r] + p] = c;
        }
    }
}

// ============================================================
// Aggregation: per node, all 8 batches, gather-max - x
// block = 128 threads (one per channel), grid = N
// ============================================================
__global__ void __launch_bounds__(128) aggregate_kernel(const float* __restrict__ x) {
    const int i = blockIdx.x;
    const int c = threadIdx.x;
    const int s = g_off[i];
    const int e = g_off[i + 1];

    float m[Bn];
#pragma unroll
    for (int b = 0; b < Bn; b++) m[b] = -INFINITY;

    int k = s;
    // 4 neighbors x 8 batches = 32 independent loads in flight
    for (; k + 4 <= e; k += 4) {
        int j0 = g_csr[k + 0];
        int j1 = g_csr[k + 1];
        int j2 = g_csr[k + 2];
        int j3 = g_csr[k + 3];
        size_t o0 = (size_t)j0 * Cn + c;
        size_t o1 = (size_t)j1 * Cn + c;
        size_t o2 = (size_t)j2 * Cn + c;
        size_t o3 = (size_t)j3 * Cn + c;
#pragma unroll
        for (int b = 0; b < Bn; b++) {
            size_t xb = (size_t)b * Nn * Cn;
            float v0 = __ldg(&x[xb + o0]);
            float v1 = __ldg(&x[xb + o1]);
            float v2 = __ldg(&x[xb + o2]);
            float v3 = __ldg(&x[xb + o3]);
            m[b] = fmaxf(m[b], fmaxf(fmaxf(v0, v1), fmaxf(v2, v3)));
        }
    }
    for (; k < e; k++) {
        int j = g_csr[k];
        size_t o = (size_t)j * Cn + c;
#pragma unroll
        for (int b = 0; b < Bn; b++)
            m[b] = fmaxf(m[b], __ldg(&x[(size_t)b * Nn * Cn + o]));
    }

    const bool none = (s == e);
    const size_t obase = (size_t)i * Cn + c;
#pragma unroll
    for (int b = 0; b < Bn; b++) {
        size_t idx = (size_t)b * Nn * Cn + obase;
        float v = none ? 0.0f : m[b];
        g_aggr[idx] = v - x[idx];
    }
}

// ============================================================
// GEMM (131072 x 128) @ (128 x 256) + bias, exact-erf GELU
// packed f32x2 FMA (Blackwell FFMA2) for 2x fp32 throughput
// ============================================================
union F2U { float2 f; unsigned long long u; };

__device__ __forceinline__ float2 ffma2(float2 a, float2 b, float2 c) {
    F2U A, Bv, Cv, D;
    A.f = a; Bv.f = b; Cv.f = c;
    asm("fma.rn.f32x2 %0, %1, %2, %3;" : "=l"(D.u) : "l"(A.u), "l"(Bv.u), "l"(Cv.u));
    return D.f;
}

__device__ __forceinline__ float gelu_exact(float v) {
    return 0.5f * v * (1.0f + erff(v * 0.70710678118654752f));
}

#define TM 128
#define TN 64
#define TK 32

__global__ void __launch_bounds__(256) gemm_kernel(const float* __restrict__ Wm,
                                                   const float* __restrict__ bias,
                                                   float* __restrict__ out) {
    __shared__ float As[TK][TM + 4];   // [k][m]
    __shared__ float Ws[TK][TN];

    const int tid = threadIdx.x;
    const int tx = tid & 15;   // col group: 4 cols
    const int ty = tid >> 4;   // row group: 8 rows
    const size_t m0 = (size_t)blockIdx.x * TM;
    const int n0 = blockIdx.y * TN;

    float2 acc[4][4];
#pragma unroll
    for (int rp = 0; rp < 4; rp++)
#pragma unroll
        for (int c2 = 0; c2 < 4; c2++) acc[rp][c2] = make_float2(0.f, 0.f);

    for (int kc = 0; kc < Cn; kc += TK) {
        // load A tile: 128 rows x 32 k = 1024 float4
#pragma unroll
        for (int it = 0; it < 4; it++) {
            int idx = tid + it * 256;
            int r = idx >> 3;
            int kq = (idx & 7) << 2;
            float4 v = *(const float4*)&g_aggr[(m0 + r) * Cn + kc + kq];
            As[kq + 0][r] = v.x;
            As[kq + 1][r] = v.y;
            As[kq + 2][r] = v.z;
            As[kq + 3][r] = v.w;
        }
        // load W tile: 32 k x 64 cols = 512 float4
#pragma unroll
        for (int it = 0; it < 2; it++) {
            int idx = tid + it * 256;
            int kk = idx >> 4;
            int cq = (idx & 15) << 2;
            *(float4*)&Ws[kk][cq] = *(const float4*)&Wm[(size_t)(kc + kk) * OUTn + n0 + cq];
        }
        __syncthreads();

#pragma unroll
        for (int kk = 0; kk < TK; kk++) {
            float4 a0 = *(const float4*)&As[kk][ty * 8];
            float4 a1 = *(const float4*)&As[kk][ty * 8 + 4];
            float4 w  = *(const float4*)&Ws[kk][tx * 4];
            float2 ap[4] = { {a0.x, a0.y}, {a0.z, a0.w}, {a1.x, a1.y}, {a1.z, a1.w} };
            float2 wp[4] = { {w.x, w.x}, {w.y, w.y}, {w.z, w.z}, {w.w, w.w} };
#pragma unroll
            for (int rp = 0; rp < 4; rp++)
#pragma unroll
                for (int c2 = 0; c2 < 4; c2++)
                    acc[rp][c2] = ffma2(ap[rp], wp[c2], acc[rp][c2]);
        }
        __syncthreads();
    }

    float bv[4];
#pragma unroll
    for (int c2 = 0; c2 < 4; c2++) bv[c2] = bias[n0 + tx * 4 + c2];

#pragma unroll
    for (int rp = 0; rp < 4; rp++) {
        size_t m = m0 + (size_t)ty * 8 + rp * 2;
        float4 o0, o1;
        o0.x = gelu_exact(acc[rp][0].x + bv[0]);
        o0.y = gelu_exact(acc[rp][1].x + bv[1]);
        o0.z = gelu_exact(acc[rp][2].x + bv[2]);
        o0.w = gelu_exact(acc[rp][3].x + bv[3]);
        o1.x = gelu_exact(acc[rp][0].y + bv[0]);
        o1.y = gelu_exact(acc[rp][1].y + bv[1]);
        o1.z = gelu_exact(acc[rp][2].y + bv[2]);
        o1.w = gelu_exact(acc[rp][3].y + bv[3]);
        *(float4*)&out[m * OUTn + n0 + tx * 4]       = o0;
        *(float4*)&out[(m + 1) * OUTn + n0 + tx * 4] = o1;
    }
}

// ============================================================
extern "C" void kernel_launch(void* const* d_in, const int* in_sizes, int n_in,
                              void* d_out, int out_size) {
    const float* x    = (const float*)d_in[0];
    const void*  ei   = d_in[1];
    const float* Wm   = (const float*)d_in[2];
    const float* bias = (const float*)d_in[3];
    float*       out  = (float*)d_out;

    detect_kernel<<<1, 1>>>((const unsigned int*)ei);
    init_kernel<<<(Nn + 255) / 256, 256>>>();
    count_kernel<<<En / 256, 256>>>(ei);
    scan_kernel<<<1, 1024>>>();
    scatter_kernel<<<En / 256, 256>>>(ei);
    aggregate_kernel<<<Nn, 128>>>(x);
    dim3 g((Bn * Nn) / TM, OUTn / TN);
    gemm_kernel<<<g, 256>>>(Wm, bias, out);
}